// round 3
// baseline (speedup 1.0000x reference)
#include <cuda_runtime.h>

#define WIRES    4
#define LAYERS   3
#define PATCHES  196
#define FEATS    784
#define CLASSES  10

// RX(theta) on one qubit of a 2-qubit substate: rotate the (i,j) amp pair.
// mat = [[c, -i s],[ -i s, c]]
__device__ __forceinline__ void rx_pair(float* re, float* im, int i, int j,
                                        float c, float s) {
    float r0 = re[i], i0 = im[i], r1 = re[j], i1 = im[j];
    re[i] = c * r0 + s * i1;
    im[i] = c * i0 - s * r1;
    re[j] = c * r1 + s * i0;
    im[j] = c * i1 - s * r0;
}

__global__ __launch_bounds__(256)
void quanv_fused_kernel(const float* __restrict__ x,    // [1024,1,28,28]
                        const float* __restrict__ qp,   // [3,4]
                        const float* __restrict__ W,    // [10,784]
                        const float* __restrict__ bias, // [10]
                        float* __restrict__ out)        // [1024,10]
{
    __shared__ float feats[FEATS];
    __shared__ float s_logits[CLASSES];
    __shared__ float s_cp[8], s_sp[8];   // RZ phases, layers 0..1 (layer 2 RZ is a dead phase)
    __shared__ float s_lse;

    const int bidx = blockIdx.x;
    const int tid  = threadIdx.x;

    if (tid < 8) {
        float phi = qp[tid] * 0.5f;
        s_cp[tid] = cosf(phi);
        s_sp[tid] = sinf(phi);
    }
    __syncthreads();

    if (tid < PATCHES) {
        const int r = tid / 14, c = tid % 14;
        const float* xb = x + (size_t)bidx * 784;
        // patch pixels in reference order: [tl, tr, bl, br] -> wires 0..3
        float2 top = *(const float2*)(xb + (2 * r) * 28 + 2 * c);
        float2 bot = *(const float2*)(xb + (2 * r + 1) * 28 + 2 * c);
        float ang[4] = {top.x, top.y, bot.x, bot.y};

        float cs[4], sn[4];
#pragma unroll
        for (int w = 0; w < 4; w++) {
            float h = ang[w] * 0.5f;
            cs[w] = cosf(h);
            sn[w] = sinf(h);
        }

        // Two independent 2-qubit substates: s=0 -> wires (0,1), s=1 -> wires (2,3).
        // amp index = hi_bit*2 + lo_bit (hi = wire 2s, lo = wire 2s+1)
        float re[2][4], im[2][4];
#pragma unroll
        for (int s = 0; s < 2; s++) {
#pragma unroll
            for (int i = 0; i < 4; i++) { re[s][i] = 0.f; im[s][i] = 0.f; }
            re[s][0] = 1.f;
        }

#pragma unroll
        for (int layer = 0; layer < LAYERS; layer++) {
#pragma unroll
            for (int s = 0; s < 2; s++) {
                float ch = cs[2 * s],     sh = sn[2 * s];      // hi wire (2s)
                float cl = cs[2 * s + 1], sl = sn[2 * s + 1];  // lo wire (2s+1)
                // RX on hi wire: pairs (0,2),(1,3)
                rx_pair(re[s], im[s], 0, 2, ch, sh);
                rx_pair(re[s], im[s], 1, 3, ch, sh);
                // RX on lo wire: pairs (0,1),(2,3)
                rx_pair(re[s], im[s], 0, 1, cl, sl);
                rx_pair(re[s], im[s], 2, 3, cl, sl);
                // CNOT(hi -> lo): ctrl hi=1 -> swap amps 2<->3
                float t;
                t = re[s][2]; re[s][2] = re[s][3]; re[s][3] = t;
                t = im[s][2]; im[s][2] = im[s][3]; im[s][3] = t;
                // RZ on both wires (skip last layer: |amp|^2 invariant)
                if (layer < LAYERS - 1) {
                    // hi wire phase: bit1 of amp index
                    float cph = s_cp[layer * 4 + 2 * s], sph = s_sp[layer * 4 + 2 * s];
                    // lo wire phase: bit0
                    float cpl = s_cp[layer * 4 + 2 * s + 1], spl = s_sp[layer * 4 + 2 * s + 1];
#pragma unroll
                    for (int i = 0; i < 4; i++) {
                        float sh_ = (i & 2) ? sph : -sph;  // bit=1 -> e^{+i phi/2}
                        float r0 = re[s][i], i0 = im[s][i];
                        re[s][i] = cph * r0 - sh_ * i0;
                        im[s][i] = cph * i0 + sh_ * r0;
                        float sl_ = (i & 1) ? spl : -spl;
                        r0 = re[s][i]; i0 = im[s][i];
                        re[s][i] = cpl * r0 - sl_ * i0;
                        im[s][i] = cpl * i0 + sl_ * r0;
                    }
                }
            }
        }

        // <Z> per wire from probs of each substate
#pragma unroll
        for (int s = 0; s < 2; s++) {
            float p0 = re[s][0] * re[s][0] + im[s][0] * im[s][0];
            float p1 = re[s][1] * re[s][1] + im[s][1] * im[s][1];
            float p2 = re[s][2] * re[s][2] + im[s][2] * im[s][2];
            float p3 = re[s][3] * re[s][3] + im[s][3] * im[s][3];
            float z_hi = (p0 + p1) - (p2 + p3);   // wire 2s
            float z_lo = (p0 + p2) - (p1 + p3);   // wire 2s+1
            feats[tid * 4 + 2 * s]     = z_hi;
            feats[tid * 4 + 2 * s + 1] = z_lo;
        }
    }
    __syncthreads();

    // Logits: 8 warps, warp wp handles classes {wp, wp+8}
    const int wp = tid >> 5, lane = tid & 31;
    for (int cls = wp; cls < CLASSES; cls += 8) {
        float acc = 0.f;
        const float* Wc = W + cls * FEATS;
#pragma unroll 4
        for (int i = lane; i < FEATS; i += 32)
            acc = fmaf(feats[i], Wc[i], acc);
#pragma unroll
        for (int off = 16; off > 0; off >>= 1)
            acc += __shfl_down_sync(0xffffffffu, acc, off);
        if (lane == 0) s_logits[cls] = acc + bias[cls];
    }
    __syncthreads();

    if (tid == 0) {
        float m = s_logits[0];
#pragma unroll
        for (int c2 = 1; c2 < CLASSES; c2++) m = fmaxf(m, s_logits[c2]);
        float sum = 0.f;
#pragma unroll
        for (int c2 = 0; c2 < CLASSES; c2++) sum += expf(s_logits[c2] - m);
        s_lse = m + logf(sum);
    }
    __syncthreads();

    if (tid < CLASSES)
        out[(size_t)bidx * CLASSES + tid] = s_logits[tid] - s_lse;
}

extern "C" void kernel_launch(void* const* d_in, const int* in_sizes, int n_in,
                              void* d_out, int out_size) {
    const float* x  = (const float*)d_in[0];   // [1024,1,28,28]
    const float* qp = (const float*)d_in[1];   // [3,4]
    const float* W  = (const float*)d_in[2];   // [10,784]
    const float* b  = (const float*)d_in[3];   // [10]
    float* out = (float*)d_out;                // [1024,10]
    quanv_fused_kernel<<<1024, 256>>>(x, qp, W, b, out);
}

// round 4
// speedup vs baseline: 1.3851x; 1.3851x over previous
#include <cuda_runtime.h>

#define LAYERS   3
#define PATCHES  196
#define FEATS    784
#define CLASSES  10

// RX rotation on an amplitude pair: a_i' = c a_i - i s a_j ; a_j' = c a_j - i s a_i
__device__ __forceinline__ void rx_pair(float* re, float* im, int i, int j,
                                        float c, float s) {
    float r0 = re[i], i0 = im[i], r1 = re[j], i1 = im[j];
    re[i] = fmaf(c, r0,  s * i1);
    im[i] = fmaf(c, i0, -s * r1);
    re[j] = fmaf(c, r1,  s * i0);
    im[j] = fmaf(c, i1, -s * r0);
}

__global__ __launch_bounds__(256)
void quanv_fused_kernel(const float* __restrict__ x,    // [1024,1,28,28]
                        const float* __restrict__ qp,   // [3,4]
                        const float* __restrict__ W,    // [10,784]
                        const float* __restrict__ bias, // [10]
                        float* __restrict__ out)        // [1024,10]
{
    __shared__ float feats[FEATS];
    __shared__ float s_logits[CLASSES];
    // Fused RZ phase factors: layer l (0..1), substate s (0..1), amp i (0..3).
    // theta = 0.5*((i&2 ? +phi_hi : -phi_hi) + (i&1 ? +phi_lo : -phi_lo))
    __shared__ float s_phre[32], s_phim[32];   // index = l*16 + s*4 + i

    const int bidx = blockIdx.x;
    const int tid  = threadIdx.x;

    if (tid < 32) {
        int l = tid >> 4, s = (tid >> 2) & 1, i = tid & 3;
        float qh = qp[l * 4 + 2 * s];
        float ql = qp[l * 4 + 2 * s + 1];
        float th = 0.5f * (((i & 2) ? qh : -qh) + ((i & 1) ? ql : -ql));
        __sincosf(th, &s_phim[tid], &s_phre[tid]);
    }
    __syncthreads();

    if (tid < PATCHES) {
        const int r = tid / 14, c = tid % 14;
        const float* xb = x + (size_t)bidx * 784;
        float2 top = *(const float2*)(xb + (2 * r) * 28 + 2 * c);
        float2 bot = *(const float2*)(xb + (2 * r + 1) * 28 + 2 * c);
        float ang[4] = {top.x, top.y, bot.x, bot.y};

        float cs[4], sn[4];
#pragma unroll
        for (int w = 0; w < 4; w++)
            __sincosf(ang[w] * 0.5f, &sn[w], &cs[w]);

        // Two independent 2-qubit substates: s=0 -> wires(0,1), s=1 -> wires(2,3).
        // amp index i = hb*2 + lb (hb = wire 2s bit, lb = wire 2s+1 bit)
#pragma unroll
        for (int s = 0; s < 2; s++) {
            const float ch = cs[2 * s],     sh = sn[2 * s];
            const float cl = cs[2 * s + 1], sl = sn[2 * s + 1];

            // --- layer 0: RX on |00> in closed form, then CNOT(hi->lo) ---
            // post-RX:  a = (ch, -i ch sl on 01, -i sh cl on 10, -sh sl on 11)
            // CNOT swaps amps 2<->3.
            float re[4], im[4];
            re[0] =  ch * cl;  im[0] = 0.f;
            re[1] =  0.f;      im[1] = -ch * sl;
            re[2] = -sh * sl;  im[2] = 0.f;        // was amp 3
            re[3] =  0.f;      im[3] = -sh * cl;   // was amp 2

            // --- RZ layer 0 (fused both wires) ---
#pragma unroll
            for (int i = 0; i < 4; i++) {
                float pr = s_phre[s * 4 + i], pi = s_phim[s * 4 + i];
                float r0 = re[i], i0 = im[i];
                re[i] = fmaf(pr, r0, -pi * i0);
                im[i] = fmaf(pr, i0,  pi * r0);
            }

            // --- layer 1: RX both wires, CNOT, RZ ---
            rx_pair(re, im, 0, 2, ch, sh);
            rx_pair(re, im, 1, 3, ch, sh);
            rx_pair(re, im, 0, 1, cl, sl);
            rx_pair(re, im, 2, 3, cl, sl);
            { float t;
              t = re[2]; re[2] = re[3]; re[3] = t;
              t = im[2]; im[2] = im[3]; im[3] = t; }
#pragma unroll
            for (int i = 0; i < 4; i++) {
                float pr = s_phre[16 + s * 4 + i], pi = s_phim[16 + s * 4 + i];
                float r0 = re[i], i0 = im[i];
                re[i] = fmaf(pr, r0, -pi * i0);
                im[i] = fmaf(pr, i0,  pi * r0);
            }

            // --- layer 2: RX both wires. Final CNOT folded into z_lo index
            //     remap; final RZ is a dead phase under |.|^2. ---
            rx_pair(re, im, 0, 2, ch, sh);
            rx_pair(re, im, 1, 3, ch, sh);
            rx_pair(re, im, 0, 1, cl, sl);
            rx_pair(re, im, 2, 3, cl, sl);

            float p0 = fmaf(re[0], re[0], im[0] * im[0]);
            float p1 = fmaf(re[1], re[1], im[1] * im[1]);
            float p2 = fmaf(re[2], re[2], im[2] * im[2]);
            float p3 = fmaf(re[3], re[3], im[3] * im[3]);
            // CNOT would swap p2<->p3: z_hi invariant, z_lo uses swapped pair.
            float z_hi = (p0 + p1) - (p2 + p3);
            float z_lo = (p0 + p3) - (p1 + p2);
            feats[tid * 4 + 2 * s]     = z_hi;
            feats[tid * 4 + 2 * s + 1] = z_lo;
        }
    }
    __syncthreads();

    // Logits: 8 warps; warp wp covers classes {wp, wp+8}
    const int wp = tid >> 5, lane = tid & 31;
    for (int cls = wp; cls < CLASSES; cls += 8) {
        float acc = 0.f;
        const float* Wc = W + cls * FEATS;
#pragma unroll 4
        for (int i = lane; i < FEATS; i += 32)
            acc = fmaf(feats[i], Wc[i], acc);
#pragma unroll
        for (int off = 16; off > 0; off >>= 1)
            acc += __shfl_down_sync(0xffffffffu, acc, off);
        if (lane == 0) s_logits[cls] = acc + bias[cls];
    }
    __syncthreads();

    // Warp 0: parallel log_softmax over 10 logits, write output directly.
    if (wp == 0) {
        float v = (lane < CLASSES) ? s_logits[lane] : -3.4e38f;
        float m = v;
#pragma unroll
        for (int off = 16; off > 0; off >>= 1)
            m = fmaxf(m, __shfl_xor_sync(0xffffffffu, m, off));
        float e = (lane < CLASSES) ? __expf(v - m) : 0.f;
        float sum = e;
#pragma unroll
        for (int off = 16; off > 0; off >>= 1)
            sum += __shfl_xor_sync(0xffffffffu, sum, off);
        float lse = m + __logf(sum);
        if (lane < CLASSES)
            out[(size_t)bidx * CLASSES + lane] = v - lse;
    }
}

extern "C" void kernel_launch(void* const* d_in, const int* in_sizes, int n_in,
                              void* d_out, int out_size) {
    const float* x  = (const float*)d_in[0];   // [1024,1,28,28]
    const float* qp = (const float*)d_in[1];   // [3,4]
    const float* W  = (const float*)d_in[2];   // [10,784]
    const float* b  = (const float*)d_in[3];   // [10]
    float* out = (float*)d_out;                // [1024,10]
    quanv_fused_kernel<<<1024, 256>>>(x, qp, W, b, out);
}